// round 8
// baseline (speedup 1.0000x reference)
#include <cuda_runtime.h>
#include <cuda_bf16.h>
#include <cstdint>

// Problem constants (fixed by the dataset)
#define BR   32768
#define INF  512
#define OUTF 512
#define ACT_Q   64.0f             // 2^act_sf,    act_sf = 6
#define WGT_Q   256.0f            // 2^weight_sf, weight_sf = 8
#define OSCALE  6.103515625e-05f  // 2^-14

// Pre-quantized e4m3 buffers (device globals; no runtime allocation).
__device__ uint8_t g_x8[(size_t)BR * INF];     // 16 MB
__device__ uint8_t g_w8[(size_t)OUTF * INF];   // 256 KB

// ---------------------------------------------------------------------------
// Quantization: trunc toward zero to fixed point, keep top-4 significant bits
// ---------------------------------------------------------------------------
__device__ __forceinline__ float qtrunc4(float v, float q) {
    int xi = (int)(v * q);                 // C cast == trunc toward zero
    unsigned a = (xi < 0) ? (unsigned)(-xi) : (unsigned)xi;
    int bl = 32 - __clz((int)a);           // bit length (0 for a==0)
    int sh = bl - 4; if (sh < 0) sh = 0;
    unsigned t = (a >> sh) << sh;
    float f = (float)t;
    return (xi < 0) ? -f : f;
}

// pack two floats -> e4m3x2; values are exactly representable here so RN exact.
__device__ __forceinline__ uint16_t pack_e4m3x2(float hi, float lo) {
    uint16_t u;
    asm("cvt.rn.satfinite.e4m3x2.f32 %0, %1, %2;" : "=h"(u) : "f"(hi), "f"(lo));
    return u;
}

// ---------------------------------------------------------------------------
// PTX helpers (sm_103-safe: ldmatrix / mma.sync / cp.async only)
// ---------------------------------------------------------------------------
__device__ __forceinline__ uint32_t smem_u32(const void* p) {
    uint32_t a;
    asm("{ .reg .u64 t; cvta.to.shared.u64 t, %1; cvt.u32.u64 %0, t; }" : "=r"(a) : "l"(p));
    return a;
}

__device__ __forceinline__ void ldsm_x4(uint32_t& r0, uint32_t& r1, uint32_t& r2, uint32_t& r3,
                                        uint32_t addr) {
    asm volatile("ldmatrix.sync.aligned.m8n8.x4.shared.b16 {%0,%1,%2,%3}, [%4];"
                 : "=r"(r0), "=r"(r1), "=r"(r2), "=r"(r3) : "r"(addr));
}

__device__ __forceinline__ void mma_fp8(float& c0, float& c1, float& c2, float& c3,
                                        uint32_t a0, uint32_t a1, uint32_t a2, uint32_t a3,
                                        uint32_t b0, uint32_t b1) {
    asm volatile(
        "mma.sync.aligned.m16n8k32.row.col.f32.e4m3.e4m3.f32 "
        "{%0,%1,%2,%3}, {%4,%5,%6,%7}, {%8,%9}, {%0,%1,%2,%3};"
        : "+f"(c0), "+f"(c1), "+f"(c2), "+f"(c3)
        : "r"(a0), "r"(a1), "r"(a2), "r"(a3), "r"(b0), "r"(b1));
}

#define CP_ASYNC16(dst, src) \
    asm volatile("cp.async.cg.shared.global [%0], [%1], 16;" :: "r"(dst), "l"(src) : "memory")
#define CP_COMMIT()  asm volatile("cp.async.commit_group;" ::: "memory")
#define CP_WAIT(n)   asm volatile("cp.async.wait_group " #n ";" ::: "memory")

// ---------------------------------------------------------------------------
// Quantize kernels: fp32 -> top4-truncated fixed point -> e4m3
// Streaming (__ldcs) reads: don't evict the freshly written fp8 from L2.
// Each thread handles 16 consecutive elements (64B read, 16B write).
// ---------------------------------------------------------------------------
__global__ void quant_x_kernel(const float* __restrict__ src) {
    size_t base = ((size_t)blockIdx.x * 256 + threadIdx.x) * 16;
    uint16_t h[8];
    #pragma unroll
    for (int j = 0; j < 4; ++j) {
        float4 v = __ldcs(reinterpret_cast<const float4*>(src + base + j * 4));
        h[2*j + 0] = pack_e4m3x2(qtrunc4(v.y, ACT_Q), qtrunc4(v.x, ACT_Q));
        h[2*j + 1] = pack_e4m3x2(qtrunc4(v.w, ACT_Q), qtrunc4(v.z, ACT_Q));
    }
    *reinterpret_cast<uint4*>(g_x8 + base) = *reinterpret_cast<uint4*>(h);
}

__global__ void quant_w_kernel(const float* __restrict__ src) {
    size_t base = ((size_t)blockIdx.x * 256 + threadIdx.x) * 16;
    uint16_t h[8];
    #pragma unroll
    for (int j = 0; j < 4; ++j) {
        float4 v = __ldcs(reinterpret_cast<const float4*>(src + base + j * 4));
        h[2*j + 0] = pack_e4m3x2(qtrunc4(v.y, WGT_Q), qtrunc4(v.x, WGT_Q));
        h[2*j + 1] = pack_e4m3x2(qtrunc4(v.w, WGT_Q), qtrunc4(v.z, WGT_Q));
    }
    *reinterpret_cast<uint4*>(g_w8 + base) = *reinterpret_cast<uint4*>(h);
}

// ---------------------------------------------------------------------------
// GEMM: fp8 e4m3, CTA 128x128, 256 threads (8 warps = 4M x 2N), warp 32x64,
// K-chunk 64 bytes, 4-stage cp.async pipeline.  (Structure of the 76.5us run.)
// SMEM pitch 80B (64B data + 16B pad): 16B groups stride 5 mod 8 -> conflict-free.
// ---------------------------------------------------------------------------
#define NCHUNK  8                  // 512 / 64
#define PITCH   80
#define ASTAGE  (128 * PITCH)      // 10240 B
#define STAGE_B (2 * ASTAGE)       // A + B per stage = 20480 B
#define STAGES  4
#define SMEM_SZ (STAGES * STAGE_B) // 81920 B

extern __shared__ unsigned char dsmem[];

__global__ void __launch_bounds__(256, 2)
gemm_kernel(const float* __restrict__ bias, float* __restrict__ out) {
    const int tid  = threadIdx.x;
    const int lane = tid & 31;
    const int wid  = tid >> 5;
    const int warp_m = wid & 3;   // 0..3 -> M offset *32
    const int warp_n = wid >> 2;  // 0..1 -> N offset *64

    const int n0 = blockIdx.x * 128;
    const int m0 = blockIdx.y * 128;

    const uint32_t base = smem_u32(dsmem);

    // ---- cp.async geometry: per chunk, per thread: 2 A rows + 2 B rows, 16B each
    const int ldrow = tid >> 2;        // 0..63
    const int ldc   = (tid & 3) * 16;  // byte offset within 64B chunk row

    const uint8_t* srcA0 = g_x8 + (size_t)(m0 + ldrow) * INF + ldc;
    const uint8_t* srcA1 = srcA0 + (size_t)64 * INF;
    const uint8_t* srcB0 = g_w8 + (size_t)(n0 + ldrow) * INF + ldc;
    const uint8_t* srcB1 = srcB0 + (size_t)64 * INF;
    const uint32_t dstA0 = base + (uint32_t)(ldrow * PITCH + ldc);
    const uint32_t dstA1 = dstA0 + 64 * PITCH;
    const uint32_t dstB0 = dstA0 + ASTAGE;
    const uint32_t dstB1 = dstB0 + 64 * PITCH;

#define ISSUE_CHUNK(kk, st)                                                  \
    do {                                                                     \
        uint32_t so = (uint32_t)((st) * STAGE_B);                            \
        size_t ko = (size_t)(kk) * 64;                                       \
        CP_ASYNC16(dstA0 + so, srcA0 + ko);                                  \
        CP_ASYNC16(dstA1 + so, srcA1 + ko);                                  \
        CP_ASYNC16(dstB0 + so, srcB0 + ko);                                  \
        CP_ASYNC16(dstB1 + so, srcB1 + ko);                                  \
        CP_COMMIT();                                                         \
    } while (0)

    // ---- prologue: fill 3 stages
    ISSUE_CHUNK(0, 0);
    ISSUE_CHUNK(1, 1);
    ISSUE_CHUNK(2, 2);

    float acc[2][8][4];
    #pragma unroll
    for (int mt = 0; mt < 2; ++mt)
        #pragma unroll
        for (int nt = 0; nt < 8; ++nt)
            #pragma unroll
            for (int i = 0; i < 4; ++i) acc[mt][nt][i] = 0.0f;

    // ---- ldmatrix lane addressing (fp8 data viewed as b16 8x8 tiles of 16B rows)
    const uint32_t aAddr = base
        + (uint32_t)((warp_m * 32 + (lane & 7) + ((lane >> 3) & 1) * 8) * PITCH)
        + (uint32_t)((lane >> 4) * 16);
    const uint32_t bAddr = base + ASTAGE
        + (uint32_t)((warp_n * 64 + (lane & 7) + (lane >> 4) * 8) * PITCH)
        + (uint32_t)(((lane >> 3) & 1) * 16);

    // ---- main loop: 8 chunks, fully unrolled
    #pragma unroll
    for (int kk = 0; kk < NCHUNK; ++kk) {
        if (kk < NCHUNK - 2)      { CP_WAIT(2); }
        else if (kk == NCHUNK - 2){ CP_WAIT(1); }
        else                      { CP_WAIT(0); }
        __syncthreads();

        if (kk + 3 < NCHUNK) ISSUE_CHUNK(kk + 3, (kk + 3) & 3);

        const uint32_t so = (uint32_t)((kk & 3) * STAGE_B);
        #pragma unroll
        for (int ks = 0; ks < 2; ++ks) {       // two k32 steps per 64B chunk
            const uint32_t kb = (uint32_t)(ks * 32);
            uint32_t a[2][4];
            #pragma unroll
            for (int mt = 0; mt < 2; ++mt)
                ldsm_x4(a[mt][0], a[mt][1], a[mt][2], a[mt][3],
                        aAddr + so + (uint32_t)(mt * 16 * PITCH) + kb);
            uint32_t b[8][2];
            #pragma unroll
            for (int p = 0; p < 4; ++p)
                ldsm_x4(b[2*p][0], b[2*p][1], b[2*p+1][0], b[2*p+1][1],
                        bAddr + so + (uint32_t)(p * 16 * PITCH) + kb);
            #pragma unroll
            for (int mt = 0; mt < 2; ++mt)
                #pragma unroll
                for (int nt = 0; nt < 8; ++nt)
                    mma_fp8(acc[mt][nt][0], acc[mt][nt][1], acc[mt][nt][2], acc[mt][nt][3],
                            a[mt][0], a[mt][1], a[mt][2], a[mt][3],
                            b[nt][0], b[nt][1]);
        }
    }

    // ---- epilogue: scale + bias; streaming stores (out is write-once) keep
    //      the fp8 operand buffers resident in L2 for later CTA waves.
    const int nbase = n0 + warp_n * 64 + (lane & 3) * 2;
    const int mbase = m0 + warp_m * 32 + (lane >> 2);
    #pragma unroll
    for (int nt = 0; nt < 8; ++nt) {
        const int col = nbase + nt * 8;
        const float b0 = bias[col];
        const float b1 = bias[col + 1];
        #pragma unroll
        for (int h = 0; h < 2; ++h) {
            #pragma unroll
            for (int mt = 0; mt < 2; ++mt) {
                const int row = mbase + mt * 16 + h * 8;
                float2 o;
                o.x = acc[mt][nt][2*h + 0] * OSCALE + b0;
                o.y = acc[mt][nt][2*h + 1] * OSCALE + b1;
                __stcs(reinterpret_cast<float2*>(out + (size_t)row * OUTF + col), o);
            }
        }
    }
}

// ---------------------------------------------------------------------------
// Launcher
// ---------------------------------------------------------------------------
extern "C" void kernel_launch(void* const* d_in, const int* in_sizes, int n_in,
                              void* d_out, int out_size) {
    const float* x    = (const float*)d_in[0];
    const float* w    = (const float*)d_in[1];
    const float* bias = (const float*)d_in[2];
    float* out = (float*)d_out;

    cudaFuncSetAttribute(gemm_kernel, cudaFuncAttributeMaxDynamicSharedMemorySize, SMEM_SZ);

    quant_w_kernel<<<(OUTF * INF) / (256 * 16), 256>>>(w);
    quant_x_kernel<<<(BR * INF) / (256 * 16), 256>>>(x);

    dim3 grid(OUTF / 128, BR / 128);   // x = N-tile (fast), y = M-tile
    gemm_kernel<<<grid, 256, SMEM_SZ>>>(bias, out);
}

// round 9
// speedup vs baseline: 1.0004x; 1.0004x over previous
#include <cuda_runtime.h>
#include <cuda_bf16.h>
#include <cstdint>

// Problem constants (fixed by the dataset)
#define BR   32768
#define INF  512
#define OUTF 512
#define ACT_Q   64.0f             // 2^act_sf,    act_sf = 6
#define WGT_Q   256.0f            // 2^weight_sf, weight_sf = 8
#define OSCALE  6.103515625e-05f  // 2^-14

// Pre-quantized e4m3 buffers (device globals; no runtime allocation).
__device__ uint8_t g_x8[(size_t)BR * INF];     // 16 MB
__device__ uint8_t g_w8[(size_t)OUTF * INF];   // 256 KB

// ---------------------------------------------------------------------------
// Quantization: trunc toward zero to fixed point, keep top-4 significant bits
// ---------------------------------------------------------------------------
__device__ __forceinline__ float qtrunc4(float v, float q) {
    int xi = (int)(v * q);                 // C cast == trunc toward zero
    unsigned a = (xi < 0) ? (unsigned)(-xi) : (unsigned)xi;
    int bl = 32 - __clz((int)a);           // bit length (0 for a==0)
    int sh = bl - 4; if (sh < 0) sh = 0;
    unsigned t = (a >> sh) << sh;
    float f = (float)t;
    return (xi < 0) ? -f : f;
}

// pack two floats -> e4m3x2; values are exactly representable here so RN exact.
__device__ __forceinline__ uint16_t pack_e4m3x2(float hi, float lo) {
    uint16_t u;
    asm("cvt.rn.satfinite.e4m3x2.f32 %0, %1, %2;" : "=h"(u) : "f"(hi), "f"(lo));
    return u;
}

// ---------------------------------------------------------------------------
// PTX helpers (sm_103-safe: ldmatrix / mma.sync / cp.async only)
// ---------------------------------------------------------------------------
__device__ __forceinline__ uint32_t smem_u32(const void* p) {
    uint32_t a;
    asm("{ .reg .u64 t; cvta.to.shared.u64 t, %1; cvt.u32.u64 %0, t; }" : "=r"(a) : "l"(p));
    return a;
}

__device__ __forceinline__ void ldsm_x4(uint32_t& r0, uint32_t& r1, uint32_t& r2, uint32_t& r3,
                                        uint32_t addr) {
    asm volatile("ldmatrix.sync.aligned.m8n8.x4.shared.b16 {%0,%1,%2,%3}, [%4];"
                 : "=r"(r0), "=r"(r1), "=r"(r2), "=r"(r3) : "r"(addr));
}

__device__ __forceinline__ void mma_fp8(float& c0, float& c1, float& c2, float& c3,
                                        uint32_t a0, uint32_t a1, uint32_t a2, uint32_t a3,
                                        uint32_t b0, uint32_t b1) {
    asm volatile(
        "mma.sync.aligned.m16n8k32.row.col.f32.e4m3.e4m3.f32 "
        "{%0,%1,%2,%3}, {%4,%5,%6,%7}, {%8,%9}, {%0,%1,%2,%3};"
        : "+f"(c0), "+f"(c1), "+f"(c2), "+f"(c3)
        : "r"(a0), "r"(a1), "r"(a2), "r"(a3), "r"(b0), "r"(b1));
}

#define CP_ASYNC16(dst, src) \
    asm volatile("cp.async.cg.shared.global [%0], [%1], 16;" :: "r"(dst), "l"(src) : "memory")
#define CP_COMMIT()  asm volatile("cp.async.commit_group;" ::: "memory")
#define CP_WAIT(n)   asm volatile("cp.async.wait_group " #n ";" ::: "memory")

// ---------------------------------------------------------------------------
// Quantize kernels: fp32 -> top4-truncated fixed point -> e4m3
// Streaming (__ldcs) reads: don't evict the freshly written fp8 from L2.
// Each thread handles 16 consecutive elements (64B read, 16B write).
// ---------------------------------------------------------------------------
__global__ void quant_x_kernel(const float* __restrict__ src) {
    size_t base = ((size_t)blockIdx.x * 256 + threadIdx.x) * 16;
    uint16_t h[8];
    #pragma unroll
    for (int j = 0; j < 4; ++j) {
        float4 v = __ldcs(reinterpret_cast<const float4*>(src + base + j * 4));
        h[2*j + 0] = pack_e4m3x2(qtrunc4(v.y, ACT_Q), qtrunc4(v.x, ACT_Q));
        h[2*j + 1] = pack_e4m3x2(qtrunc4(v.w, ACT_Q), qtrunc4(v.z, ACT_Q));
    }
    *reinterpret_cast<uint4*>(g_x8 + base) = *reinterpret_cast<uint4*>(h);
}

__global__ void quant_w_kernel(const float* __restrict__ src) {
    size_t base = ((size_t)blockIdx.x * 256 + threadIdx.x) * 16;
    uint16_t h[8];
    #pragma unroll
    for (int j = 0; j < 4; ++j) {
        float4 v = __ldcs(reinterpret_cast<const float4*>(src + base + j * 4));
        h[2*j + 0] = pack_e4m3x2(qtrunc4(v.y, WGT_Q), qtrunc4(v.x, WGT_Q));
        h[2*j + 1] = pack_e4m3x2(qtrunc4(v.w, WGT_Q), qtrunc4(v.z, WGT_Q));
    }
    *reinterpret_cast<uint4*>(g_w8 + base) = *reinterpret_cast<uint4*>(h);
}

// ---------------------------------------------------------------------------
// GEMM: fp8 e4m3, CTA 128x128, 256 threads (8 warps = 4M x 2N), warp 32x64,
// K-chunk 64 bytes, 4-stage cp.async pipeline.  (Structure of the 76.5us run.)
// SMEM pitch 80B (64B data + 16B pad): 16B groups stride 5 mod 8 -> conflict-free.
// ---------------------------------------------------------------------------
#define NCHUNK  8                  // 512 / 64
#define PITCH   80
#define ASTAGE  (128 * PITCH)      // 10240 B
#define STAGE_B (2 * ASTAGE)       // A + B per stage = 20480 B
#define STAGES  4
#define SMEM_SZ (STAGES * STAGE_B) // 81920 B

extern __shared__ unsigned char dsmem[];

__global__ void __launch_bounds__(256, 2)
gemm_kernel(const float* __restrict__ bias, float* __restrict__ out) {
    const int tid  = threadIdx.x;
    const int lane = tid & 31;
    const int wid  = tid >> 5;
    const int warp_m = wid & 3;   // 0..3 -> M offset *32
    const int warp_n = wid >> 2;  // 0..1 -> N offset *64

    const int n0 = blockIdx.x * 128;
    const int m0 = blockIdx.y * 128;

    const uint32_t base = smem_u32(dsmem);

    // ---- cp.async geometry: per chunk, per thread: 2 A rows + 2 B rows, 16B each
    const int ldrow = tid >> 2;        // 0..63
    const int ldc   = (tid & 3) * 16;  // byte offset within 64B chunk row

    const uint8_t* srcA0 = g_x8 + (size_t)(m0 + ldrow) * INF + ldc;
    const uint8_t* srcA1 = srcA0 + (size_t)64 * INF;
    const uint8_t* srcB0 = g_w8 + (size_t)(n0 + ldrow) * INF + ldc;
    const uint8_t* srcB1 = srcB0 + (size_t)64 * INF;
    const uint32_t dstA0 = base + (uint32_t)(ldrow * PITCH + ldc);
    const uint32_t dstA1 = dstA0 + 64 * PITCH;
    const uint32_t dstB0 = dstA0 + ASTAGE;
    const uint32_t dstB1 = dstB0 + 64 * PITCH;

#define ISSUE_CHUNK(kk, st)                                                  \
    do {                                                                     \
        uint32_t so = (uint32_t)((st) * STAGE_B);                            \
        size_t ko = (size_t)(kk) * 64;                                       \
        CP_ASYNC16(dstA0 + so, srcA0 + ko);                                  \
        CP_ASYNC16(dstA1 + so, srcA1 + ko);                                  \
        CP_ASYNC16(dstB0 + so, srcB0 + ko);                                  \
        CP_ASYNC16(dstB1 + so, srcB1 + ko);                                  \
        CP_COMMIT();                                                         \
    } while (0)

    // ---- prologue: fill 3 stages
    ISSUE_CHUNK(0, 0);
    ISSUE_CHUNK(1, 1);
    ISSUE_CHUNK(2, 2);

    float acc[2][8][4];
    #pragma unroll
    for (int mt = 0; mt < 2; ++mt)
        #pragma unroll
        for (int nt = 0; nt < 8; ++nt)
            #pragma unroll
            for (int i = 0; i < 4; ++i) acc[mt][nt][i] = 0.0f;

    // ---- ldmatrix lane addressing (fp8 data viewed as b16 8x8 tiles of 16B rows)
    const uint32_t aAddr = base
        + (uint32_t)((warp_m * 32 + (lane & 7) + ((lane >> 3) & 1) * 8) * PITCH)
        + (uint32_t)((lane >> 4) * 16);
    const uint32_t bAddr = base + ASTAGE
        + (uint32_t)((warp_n * 64 + (lane & 7) + (lane >> 4) * 8) * PITCH)
        + (uint32_t)(((lane >> 3) & 1) * 16);

    // ---- main loop: 8 chunks, fully unrolled
    #pragma unroll
    for (int kk = 0; kk < NCHUNK; ++kk) {
        if (kk < NCHUNK - 2)      { CP_WAIT(2); }
        else if (kk == NCHUNK - 2){ CP_WAIT(1); }
        else                      { CP_WAIT(0); }
        __syncthreads();

        if (kk + 3 < NCHUNK) ISSUE_CHUNK(kk + 3, (kk + 3) & 3);

        const uint32_t so = (uint32_t)((kk & 3) * STAGE_B);
        #pragma unroll
        for (int ks = 0; ks < 2; ++ks) {       // two k32 steps per 64B chunk
            const uint32_t kb = (uint32_t)(ks * 32);
            uint32_t a[2][4];
            #pragma unroll
            for (int mt = 0; mt < 2; ++mt)
                ldsm_x4(a[mt][0], a[mt][1], a[mt][2], a[mt][3],
                        aAddr + so + (uint32_t)(mt * 16 * PITCH) + kb);
            uint32_t b[8][2];
            #pragma unroll
            for (int p = 0; p < 4; ++p)
                ldsm_x4(b[2*p][0], b[2*p][1], b[2*p+1][0], b[2*p+1][1],
                        bAddr + so + (uint32_t)(p * 16 * PITCH) + kb);
            #pragma unroll
            for (int mt = 0; mt < 2; ++mt)
                #pragma unroll
                for (int nt = 0; nt < 8; ++nt)
                    mma_fp8(acc[mt][nt][0], acc[mt][nt][1], acc[mt][nt][2], acc[mt][nt][3],
                            a[mt][0], a[mt][1], a[mt][2], a[mt][3],
                            b[nt][0], b[nt][1]);
        }
    }

    // ---- epilogue: scale + bias; streaming stores (out is write-once) keep
    //      the fp8 operand buffers resident in L2 for later CTA waves.
    const int nbase = n0 + warp_n * 64 + (lane & 3) * 2;
    const int mbase = m0 + warp_m * 32 + (lane >> 2);
    #pragma unroll
    for (int nt = 0; nt < 8; ++nt) {
        const int col = nbase + nt * 8;
        const float b0 = bias[col];
        const float b1 = bias[col + 1];
        #pragma unroll
        for (int h = 0; h < 2; ++h) {
            #pragma unroll
            for (int mt = 0; mt < 2; ++mt) {
                const int row = mbase + mt * 16 + h * 8;
                float2 o;
                o.x = acc[mt][nt][2*h + 0] * OSCALE + b0;
                o.y = acc[mt][nt][2*h + 1] * OSCALE + b1;
                __stcs(reinterpret_cast<float2*>(out + (size_t)row * OUTF + col), o);
            }
        }
    }
}

// ---------------------------------------------------------------------------
// Launcher
// ---------------------------------------------------------------------------
extern "C" void kernel_launch(void* const* d_in, const int* in_sizes, int n_in,
                              void* d_out, int out_size) {
    const float* x    = (const float*)d_in[0];
    const float* w    = (const float*)d_in[1];
    const float* bias = (const float*)d_in[2];
    float* out = (float*)d_out;

    cudaFuncSetAttribute(gemm_kernel, cudaFuncAttributeMaxDynamicSharedMemorySize, SMEM_SZ);

    quant_w_kernel<<<(OUTF * INF) / (256 * 16), 256>>>(w);
    quant_x_kernel<<<(BR * INF) / (256 * 16), 256>>>(x);

    dim3 grid(OUTF / 128, BR / 128);   // x = N-tile (fast), y = M-tile
    gemm_kernel<<<grid, 256, SMEM_SZ>>>(bias, out);
}

// round 10
// speedup vs baseline: 1.0220x; 1.0216x over previous
#include <cuda_runtime.h>
#include <cuda_bf16.h>
#include <cstdint>

// Problem constants (fixed by the dataset)
#define BR   32768
#define INF  512
#define OUTF 512
#define ACT_Q   64.0f             // 2^act_sf,    act_sf = 6
#define WGT_Q   256.0f            // 2^weight_sf, weight_sf = 8
#define OSCALE  6.103515625e-05f  // 2^-14

// Pre-quantized e4m3 buffers (device globals; no runtime allocation).
__device__ uint8_t g_x8[(size_t)BR * INF];     // 16 MB
__device__ uint8_t g_w8[(size_t)OUTF * INF];   // 256 KB

// ---------------------------------------------------------------------------
// Quantization: trunc toward zero to fixed point, keep top-4 significant bits
// ---------------------------------------------------------------------------
__device__ __forceinline__ float qtrunc4(float v, float q) {
    int xi = (int)(v * q);                 // C cast == trunc toward zero
    unsigned a = (xi < 0) ? (unsigned)(-xi) : (unsigned)xi;
    int bl = 32 - __clz((int)a);           // bit length (0 for a==0)
    int sh = bl - 4; if (sh < 0) sh = 0;
    unsigned t = (a >> sh) << sh;
    float f = (float)t;
    return (xi < 0) ? -f : f;
}

// pack two floats -> e4m3x2; values are exactly representable here so RN exact.
__device__ __forceinline__ uint16_t pack_e4m3x2(float hi, float lo) {
    uint16_t u;
    asm("cvt.rn.satfinite.e4m3x2.f32 %0, %1, %2;" : "=h"(u) : "f"(hi), "f"(lo));
    return u;
}

// ---------------------------------------------------------------------------
// PTX helpers (sm_103-safe: ldmatrix / mma.sync / cp.async only)
// ---------------------------------------------------------------------------
__device__ __forceinline__ uint32_t smem_u32(const void* p) {
    uint32_t a;
    asm("{ .reg .u64 t; cvta.to.shared.u64 t, %1; cvt.u32.u64 %0, t; }" : "=r"(a) : "l"(p));
    return a;
}

__device__ __forceinline__ void ldsm_x4(uint32_t& r0, uint32_t& r1, uint32_t& r2, uint32_t& r3,
                                        uint32_t addr) {
    asm volatile("ldmatrix.sync.aligned.m8n8.x4.shared.b16 {%0,%1,%2,%3}, [%4];"
                 : "=r"(r0), "=r"(r1), "=r"(r2), "=r"(r3) : "r"(addr));
}

__device__ __forceinline__ void mma_fp8(float& c0, float& c1, float& c2, float& c3,
                                        uint32_t a0, uint32_t a1, uint32_t a2, uint32_t a3,
                                        uint32_t b0, uint32_t b1) {
    asm volatile(
        "mma.sync.aligned.m16n8k32.row.col.f32.e4m3.e4m3.f32 "
        "{%0,%1,%2,%3}, {%4,%5,%6,%7}, {%8,%9}, {%0,%1,%2,%3};"
        : "+f"(c0), "+f"(c1), "+f"(c2), "+f"(c3)
        : "r"(a0), "r"(a1), "r"(a2), "r"(a3), "r"(b0), "r"(b1));
}

#define CP_ASYNC16(dst, src) \
    asm volatile("cp.async.cg.shared.global [%0], [%1], 16;" :: "r"(dst), "l"(src) : "memory")
#define CP_COMMIT()  asm volatile("cp.async.commit_group;" ::: "memory")
#define CP_WAIT(n)   asm volatile("cp.async.wait_group " #n ";" ::: "memory")

// ---------------------------------------------------------------------------
// Merged quantize kernel. W-blocks FIRST (blockIdx < QW_BLOCKS) so the tiny
// weight grid runs inside wave 1, fully overlapped with the x quantization.
// Each thread: 16 consecutive elements (64B read, 16B write), streaming reads.
// ---------------------------------------------------------------------------
#define QW_BLOCKS ((OUTF * INF) / (256 * 16))    // 64
#define QX_BLOCKS ((BR * INF) / (256 * 16))      // 4096

__global__ void quant_kernel(const float* __restrict__ x, const float* __restrict__ w) {
    const bool isW = (blockIdx.x < QW_BLOCKS);
    const float* src = isW ? w : x;
    uint8_t* dst = isW ? g_w8 : g_x8;
    const float q = isW ? WGT_Q : ACT_Q;
    size_t bid = isW ? (size_t)blockIdx.x : (size_t)(blockIdx.x - QW_BLOCKS);
    size_t base = (bid * 256 + threadIdx.x) * 16;
    uint16_t h[8];
    #pragma unroll
    for (int j = 0; j < 4; ++j) {
        float4 v = __ldcs(reinterpret_cast<const float4*>(src + base + j * 4));
        h[2*j + 0] = pack_e4m3x2(qtrunc4(v.y, q), qtrunc4(v.x, q));
        h[2*j + 1] = pack_e4m3x2(qtrunc4(v.w, q), qtrunc4(v.z, q));
    }
    *reinterpret_cast<uint4*>(dst + base) = *reinterpret_cast<uint4*>(h);
}

// ---------------------------------------------------------------------------
// GEMM: fp8 e4m3, CTA 128x128, 256 threads (8 warps = 4M x 2N), warp 32x64,
// K-chunk 64 bytes, 5-stage cp.async pipeline (mainloop identical to 75.8us).
// SMEM pitch 80B (64B data + 16B pad): 16B groups stride 5 mod 8 -> conflict-free.
// ---------------------------------------------------------------------------
#define NCHUNK  8                  // 512 / 64
#define PITCH   80
#define ASTAGE  (128 * PITCH)      // 10240 B
#define STAGE_B (2 * ASTAGE)       // A + B per stage = 20480 B
#define STAGES  5
#define SMEM_SZ (STAGES * STAGE_B) // 102400 B

extern __shared__ unsigned char dsmem[];

__global__ void __launch_bounds__(256, 2)
gemm_kernel(const float* __restrict__ bias, float* __restrict__ out) {
    const int tid  = threadIdx.x;
    const int lane = tid & 31;
    const int wid  = tid >> 5;
    const int warp_m = wid & 3;   // 0..3 -> M offset *32
    const int warp_n = wid >> 2;  // 0..1 -> N offset *64

    const int n0 = blockIdx.x * 128;
    const int m0 = blockIdx.y * 128;

    const uint32_t base = smem_u32(dsmem);

    // ---- cp.async geometry: per chunk, per thread: 2 A rows + 2 B rows, 16B each
    const int ldrow = tid >> 2;        // 0..63
    const int ldc   = (tid & 3) * 16;  // byte offset within 64B chunk row

    const uint8_t* srcA0 = g_x8 + (size_t)(m0 + ldrow) * INF + ldc;
    const uint8_t* srcA1 = srcA0 + (size_t)64 * INF;
    const uint8_t* srcB0 = g_w8 + (size_t)(n0 + ldrow) * INF + ldc;
    const uint8_t* srcB1 = srcB0 + (size_t)64 * INF;
    const uint32_t dstA0 = base + (uint32_t)(ldrow * PITCH + ldc);
    const uint32_t dstA1 = dstA0 + 64 * PITCH;
    const uint32_t dstB0 = dstA0 + ASTAGE;
    const uint32_t dstB1 = dstB0 + 64 * PITCH;

#define ISSUE_CHUNK(kk, st)                                                  \
    do {                                                                     \
        uint32_t so = (uint32_t)((st) * STAGE_B);                            \
        size_t ko = (size_t)(kk) * 64;                                       \
        CP_ASYNC16(dstA0 + so, srcA0 + ko);                                  \
        CP_ASYNC16(dstA1 + so, srcA1 + ko);                                  \
        CP_ASYNC16(dstB0 + so, srcB0 + ko);                                  \
        CP_ASYNC16(dstB1 + so, srcB1 + ko);                                  \
        CP_COMMIT();                                                         \
    } while (0)

    // ---- prologue: fill 4 of 5 stages
    ISSUE_CHUNK(0, 0);
    ISSUE_CHUNK(1, 1);
    ISSUE_CHUNK(2, 2);
    ISSUE_CHUNK(3, 3);

    float acc[2][8][4];
    #pragma unroll
    for (int mt = 0; mt < 2; ++mt)
        #pragma unroll
        for (int nt = 0; nt < 8; ++nt)
            #pragma unroll
            for (int i = 0; i < 4; ++i) acc[mt][nt][i] = 0.0f;

    // ---- ldmatrix lane addressing (fp8 data viewed as b16 8x8 tiles of 16B rows)
    const uint32_t aAddr = base
        + (uint32_t)((warp_m * 32 + (lane & 7) + ((lane >> 3) & 1) * 8) * PITCH)
        + (uint32_t)((lane >> 4) * 16);
    const uint32_t bAddr = base + ASTAGE
        + (uint32_t)((warp_n * 64 + (lane & 7) + (lane >> 4) * 8) * PITCH)
        + (uint32_t)(((lane >> 3) & 1) * 16);

    // ---- main loop: 8 chunks, fully unrolled
    #pragma unroll
    for (int kk = 0; kk < NCHUNK; ++kk) {
        if (kk < NCHUNK - 3)      { CP_WAIT(3); }
        else if (kk == NCHUNK - 3){ CP_WAIT(2); }
        else if (kk == NCHUNK - 2){ CP_WAIT(1); }
        else                      { CP_WAIT(0); }
        __syncthreads();

        if (kk + 4 < NCHUNK) ISSUE_CHUNK(kk + 4, (kk + 4) % STAGES);

        const uint32_t so = (uint32_t)((kk % STAGES) * STAGE_B);
        #pragma unroll
        for (int ks = 0; ks < 2; ++ks) {       // two k32 steps per 64B chunk
            const uint32_t kb = (uint32_t)(ks * 32);
            uint32_t a[2][4];
            #pragma unroll
            for (int mt = 0; mt < 2; ++mt)
                ldsm_x4(a[mt][0], a[mt][1], a[mt][2], a[mt][3],
                        aAddr + so + (uint32_t)(mt * 16 * PITCH) + kb);
            uint32_t b[8][2];
            #pragma unroll
            for (int p = 0; p < 4; ++p)
                ldsm_x4(b[2*p][0], b[2*p][1], b[2*p+1][0], b[2*p+1][1],
                        bAddr + so + (uint32_t)(p * 16 * PITCH) + kb);
            #pragma unroll
            for (int mt = 0; mt < 2; ++mt)
                #pragma unroll
                for (int nt = 0; nt < 8; ++nt)
                    mma_fp8(acc[mt][nt][0], acc[mt][nt][1], acc[mt][nt][2], acc[mt][nt][3],
                            a[mt][0], a[mt][1], a[mt][2], a[mt][3],
                            b[nt][0], b[nt][1]);
        }
    }

    // ---- epilogue: scale + bias; streaming stores (out is write-once) keep
    //      the fp8 operand buffers resident in L2 for later CTA waves.
    const int nbase = n0 + warp_n * 64 + (lane & 3) * 2;
    const int mbase = m0 + warp_m * 32 + (lane >> 2);
    #pragma unroll
    for (int nt = 0; nt < 8; ++nt) {
        const int col = nbase + nt * 8;
        const float b0 = bias[col];
        const float b1 = bias[col + 1];
        #pragma unroll
        for (int h = 0; h < 2; ++h) {
            #pragma unroll
            for (int mt = 0; mt < 2; ++mt) {
                const int row = mbase + mt * 16 + h * 8;
                float2 o;
                o.x = acc[mt][nt][2*h + 0] * OSCALE + b0;
                o.y = acc[mt][nt][2*h + 1] * OSCALE + b1;
                __stcs(reinterpret_cast<float2*>(out + (size_t)row * OUTF + col), o);
            }
        }
    }
}

// ---------------------------------------------------------------------------
// Launcher
// ---------------------------------------------------------------------------
extern "C" void kernel_launch(void* const* d_in, const int* in_sizes, int n_in,
                              void* d_out, int out_size) {
    const float* x    = (const float*)d_in[0];
    const float* w    = (const float*)d_in[1];
    const float* bias = (const float*)d_in[2];
    float* out = (float*)d_out;

    cudaFuncSetAttribute(gemm_kernel, cudaFuncAttributeMaxDynamicSharedMemorySize, SMEM_SZ);

    quant_kernel<<<QW_BLOCKS + QX_BLOCKS, 256>>>(x, w);

    dim3 grid(OUTF / 128, BR / 128);   // x = N-tile (fast), y = M-tile
    gemm_kernel<<<grid, 256, SMEM_SZ>>>(bias, out);
}